// round 6
// baseline (speedup 1.0000x reference)
#include <cuda_runtime.h>
#include <cstdint>

#define B_   16
#define N_   1024
#define M_   12
#define FB_  32
#define F_   128
#define ROWS_TOT (B_ * N_)   // 16384

__device__ float g_p[ROWS_TOT];
__device__ float g_s[ROWS_TOT];
__device__ float g_Y[ROWS_TOT * F_];   // unscaled GEMM result (8 MB)

static __device__ __forceinline__ uint32_t s2u(const void* p) {
    return (uint32_t)__cvta_generic_to_shared(p);
}

// ---------------------------------------------------------------------------
// Kernel A: merged bond + GEMM.
//   blockIdx % 3 == 0  -> GEMM block   (256 of them, 64 rows each)
//   else               -> bond block   (512 of them, 32 rows each)
// Interleaved so bond's DRAM streaming overlaps the GEMM's fma work.
// Dynamic smem 80 KB: sA2 (float2[64][128], duplicated A) + sW (float[32][128]).
// ---------------------------------------------------------------------------
extern __shared__ float dsm[];

__global__ __launch_bounds__(256) void merged_kernel(
    const float* __restrict__ atom, const int* __restrict__ adj,
    const float* __restrict__ bond, const float* __restrict__ W)
{
    int tid  = threadIdx.x;
    int wid  = tid >> 5;
    int lane = tid & 31;

    if (blockIdx.x % 3 != 0) {
        // ================= bond path: 32 rows, 4 rows per warp =============
        int blk  = (blockIdx.x / 3) * 2 + (blockIdx.x % 3) - 1;   // 0..511
        int row0 = (blk * 8 + wid) * 4;
        int grp  = lane >> 3;
        int sub  = lane & 7;
        const float* b = bond + (size_t)row0 * (M_ * FB_);

        float4 v[4][3];
#pragma unroll
        for (int j = 0; j < 4; ++j)
#pragma unroll
            for (int i = 0; i < 3; ++i)
                v[j][i] = *(const float4*)(b + j * (M_ * FB_)
                                             + ((((i << 2) + grp) << 5) + (sub << 2)));

        float sum[4], prod[4];
#pragma unroll
        for (int j = 0; j < 4; ++j) { sum[j] = 0.f; prod[j] = 1.f; }
#pragma unroll
        for (int i = 0; i < 3; ++i) {
            float s[4];
#pragma unroll
            for (int j = 0; j < 4; ++j) {
                float4 u = v[j][i];
                s[j] = u.x*u.x + u.y*u.y + u.z*u.z + u.w*u.w;
            }
#pragma unroll
            for (int off = 1; off <= 4; off <<= 1)
#pragma unroll
                for (int j = 0; j < 4; ++j)
                    s[j] += __shfl_xor_sync(0xffffffffu, s[j], off);
#pragma unroll
            for (int j = 0; j < 4; ++j) {
                float r = 1.0f / s[j];     // (sqrt(s))^-2 == 1/s
                sum[j] += r; prod[j] *= r;
            }
        }
#pragma unroll
        for (int off = 8; off <= 16; off <<= 1)
#pragma unroll
            for (int j = 0; j < 4; ++j) {
                sum[j]  += __shfl_xor_sync(0xffffffffu, sum[j], off);
                prod[j] *= __shfl_xor_sync(0xffffffffu, prod[j], off);
            }
        if (lane < 4) {
            float S = (lane == 0) ? sum[0]  : (lane == 1) ? sum[1]  : (lane == 2) ? sum[2]  : sum[3];
            float P = (lane == 0) ? prod[0] : (lane == 1) ? prod[1] : (lane == 2) ? prod[2] : prod[3];
            float D = fmaxf(S, 1e-12f);
            float d2 = D * D, d4 = d2 * d2;
            g_p[row0 + lane] = P / (d4 * d4 * d4);
        }
        return;
    }

    // ================= GEMM path: 64 rows x 128 cols ======================
    float2* sA2 = (float2*)dsm;            // [64][128] duplicated (a,a)
    float*  sW  = dsm + 2 * 64 * F_;       // [32][128]
    int row0 = (blockIdx.x / 3) << 6;

    // ---- Build A tile (no s scaling): each warp produces 8 rows ----
#pragma unroll
    for (int rr = 0; rr < 8; ++rr) {
        int r = (wid << 3) + rr;
        int g = row0 + r;
        int b = g >> 10;
        const float* arow  = atom + ((size_t)g << 7);
        const float* abase = atom + ((size_t)b << 17);
        int myidx = (lane < M_) ? adj[(size_t)g * M_ + lane] : 0;

        float4 self = *(const float4*)(arow + (lane << 2));
        float ax = 0.f, ay = 0.f, az = 0.f, aw = 0.f;
#pragma unroll
        for (int m = 0; m < M_; ++m) {
            int idx = __shfl_sync(0xffffffffu, myidx, m) & (N_ - 1);
            float4 nb = *(const float4*)(abase + ((size_t)idx << 7) + (lane << 2));
            ax += nb.x; ay += nb.y; az += nb.z; aw += nb.w;
        }
        const float inv12 = 1.0f / 12.0f;
        float vx = self.x + ax * inv12;
        float vy = self.y + ay * inv12;
        float vz = self.z + az * inv12;
        float vw = self.w + aw * inv12;
        // store duplicated pairs: two STS.128 per row
        float4* dst = (float4*)&sA2[r * F_ + (lane << 2)];
        dst[0] = make_float4(vx, vx, vy, vy);
        dst[1] = make_float4(vz, vz, vw, vw);
    }

    float acc[8][4];   // [row][col-pair as 2 floats each... packed below]
    uint64_t pacc[8][2];
#pragma unroll
    for (int r = 0; r < 8; ++r) { pacc[r][0] = 0ull; pacc[r][1] = 0ull; }
    (void)acc;

    uint32_t a_base = s2u(sA2) + (uint32_t)((wid << 3) * F_) * 8u;  // row stride 1024B
    uint32_t w_base = s2u(sW) + (uint32_t)(lane << 4);              // lane*16B

#pragma unroll
    for (int kc = 0; kc < 4; ++kc) {
        __syncthreads();   // protects sW (and sA2 build on kc==0)
        {
            const float4* src = (const float4*)(W + (size_t)(kc << 5) * F_);
            float4* dstw = (float4*)sW;
#pragma unroll
            for (int t = 0; t < 4; ++t) dstw[tid + (t << 8)] = src[tid + (t << 8)];
        }
        __syncthreads();

        uint32_t kb8 = (uint32_t)(kc << 5) * 8u;   // byte offset of chunk in sA2 row
#pragma unroll 4
        for (int kk = 0; kk < 32; ++kk) {
            uint64_t w01, w23;
            asm("ld.shared.v2.u64 {%0,%1}, [%2];"
                : "=l"(w01), "=l"(w23) : "r"(w_base + (uint32_t)(kk << 9)));
#pragma unroll
            for (int r = 0; r < 8; ++r) {
                uint64_t a2;
                asm("ld.shared.u64 %0, [%1];"
                    : "=l"(a2) : "r"(a_base + (uint32_t)(r * F_ * 8) + kb8 + (uint32_t)(kk << 3)));
                asm("fma.rn.f32x2 %0, %1, %2, %0;" : "+l"(pacc[r][0]) : "l"(a2), "l"(w01));
                asm("fma.rn.f32x2 %0, %1, %2, %0;" : "+l"(pacc[r][1]) : "l"(a2), "l"(w23));
            }
        }
    }

    // ---- Write raw Y (no bias/relu/s) ----
#pragma unroll
    for (int r = 0; r < 8; ++r) {
        int g = row0 + (wid << 3) + r;
        float c0, c1, c2, c3;
        asm("mov.b64 {%0, %1}, %2;" : "=f"(c0), "=f"(c1) : "l"(pacc[r][0]));
        asm("mov.b64 {%0, %1}, %2;" : "=f"(c2), "=f"(c3) : "l"(pacc[r][1]));
        *(float4*)(g_Y + ((size_t)g << 7) + (lane << 2)) = make_float4(c0, c1, c2, c3);
    }
}

// ---------------------------------------------------------------------------
// Kernel B: colsum over B, u = max(colsum,eps)/p, s = u / sum_n u
// ---------------------------------------------------------------------------
__global__ void s_kernel() {
    __shared__ float red[32];
    int b = blockIdx.x, n = threadIdx.x;
    int wid = n >> 5, lane = n & 31;

    float cs = 0.f;
#pragma unroll
    for (int bb = 0; bb < B_; ++bb) cs += g_p[bb * N_ + n];
    float u = fmaxf(cs, 1e-12f) / g_p[b * N_ + n];

    float v = u;
#pragma unroll
    for (int off = 16; off; off >>= 1) v += __shfl_xor_sync(0xffffffffu, v, off);
    if (lane == 0) red[wid] = v;
    __syncthreads();
    if (wid == 0) {
        float t = red[lane];
#pragma unroll
        for (int off = 16; off; off >>= 1) t += __shfl_xor_sync(0xffffffffu, t, off);
        if (lane == 0) red[0] = 1.0f / fmaxf(t, 1e-12f);
    }
    __syncthreads();
    g_s[b * N_ + n] = u * red[0];
}

// ---------------------------------------------------------------------------
// Kernel C: epilogue  out = relu(s*Y + bias)
// ---------------------------------------------------------------------------
__global__ __launch_bounds__(256) void epilogue_kernel(
    const float* __restrict__ bias, float* __restrict__ out)
{
    int idx = blockIdx.x * 256 + threadIdx.x;      // float4 index, 524288 total
    int row = idx >> 5;
    int c4  = idx & 31;
    float s = g_s[row];
    float4 y  = *(const float4*)(g_Y + ((size_t)idx << 2));
    float4 bv = *(const float4*)(bias + (c4 << 2));
    float4 o;
    o.x = fmaxf(fmaf(s, y.x, bv.x), 0.f);
    o.y = fmaxf(fmaf(s, y.y, bv.y), 0.f);
    o.z = fmaxf(fmaf(s, y.z, bv.z), 0.f);
    o.w = fmaxf(fmaf(s, y.w, bv.w), 0.f);
    *(float4*)(out + ((size_t)idx << 2)) = o;
}

// ---------------------------------------------------------------------------
extern "C" void kernel_launch(void* const* d_in, const int* in_sizes, int n_in,
                              void* d_out, int out_size) {
    const float* atom = (const float*)d_in[0];
    const float* bond = (const float*)d_in[1];
    const int*   adj  = (const int*)d_in[2];
    const float* W    = (const float*)d_in[3];
    const float* bias = (const float*)d_in[4];
    float*       out  = (float*)d_out;

    static bool attr_done = false;
    if (!attr_done) {
        cudaFuncSetAttribute(merged_kernel,
                             cudaFuncAttributeMaxDynamicSharedMemorySize, 81920);
        attr_done = true;
    }

    merged_kernel  <<<768, 256, 81920>>>(atom, adj, bond, W);
    s_kernel       <<<B_, 1024>>>();
    epilogue_kernel<<<ROWS_TOT * F_ / 1024, 256>>>(bias, out);
}